// round 5
// baseline (speedup 1.0000x reference)
#include <cuda_runtime.h>

#define N_NODES 10000
#define N_EDGES 640000
#define DIM 128
#define HEADS 4
#define DHEAD 32

// ---- scratch (device globals; no allocation) ----
__device__ float g_qk[(size_t)N_NODES * HEADS * DIM];   // scale * (Wk^T q) per head, [n][h][c]
__device__ float g_qc[(size_t)N_NODES * HEADS];         // scale * (q . bk) per head
__device__ float g_wn[(size_t)N_NODES * HEADS * DIM];   // normalized weighted v aggregate, [n][h][c]
__device__ int   g_count[N_NODES];
__device__ int   g_start[N_NODES];
__device__ int   g_cursor[N_NODES];
__device__ int   g_elist[N_EDGES];
__device__ float g_WkT[DIM * DIM];                      // WkT[kk][c] = Wk[c][kk]
__device__ float g_M[HEADS * DIM * DIM];                // M[h*128+c][j] = sum_d Wv[c,h32+d]*Wo[h32+d,j]
__device__ float g_cb[DIM];                             // bv@Wo + bo

// ---------------- setup kernels ----------------
__global__ void zero_kernel() {
    int i = blockIdx.x * blockDim.x + threadIdx.x;
    if (i < N_NODES) g_count[i] = 0;
}

__global__ void wkt_kernel(const float* __restrict__ Wk) {
    int kk = blockIdx.x, c = threadIdx.x;
    g_WkT[kk * DIM + c] = Wk[c * DIM + kk];
}

__global__ void m_kernel(const float* __restrict__ Wv, const float* __restrict__ Wo) {
    int b = blockIdx.x;                 // b = h*128 + c
    int h = b >> 7, c = b & 127;
    int j = threadIdx.x;
    float a = 0.f;
#pragma unroll
    for (int d = 0; d < DHEAD; d++)
        a += Wv[c * DIM + h * DHEAD + d] * Wo[(h * DHEAD + d) * DIM + j];
    g_M[b * DIM + j] = a;
}

__global__ void cb_kernel(const float* __restrict__ bv, const float* __restrict__ Wo,
                          const float* __restrict__ bo) {
    int j = threadIdx.x;
    float a = bo[j];
    for (int i = 0; i < DIM; i++) a += bv[i] * Wo[i * DIM + j];
    g_cb[j] = a;
}

// ---------------- q projection + qk precompute ----------------
// block = 128 threads handles 16 nodes. 10000 % 16 == 0 -> 625 blocks, no guards.
__global__ void __launch_bounds__(128) qk_kernel(const float* __restrict__ q_nodes,
                                                 const float* __restrict__ Wq,
                                                 const float* __restrict__ bq,
                                                 const float* __restrict__ bk) {
    __shared__ float sqn[16][DIM];
    __shared__ float sq[16][DIM];
    int t = threadIdx.x;
    int n0 = blockIdx.x * 16;
#pragma unroll
    for (int i = 0; i < 16; i++) sqn[i][t] = q_nodes[(size_t)(n0 + i) * DIM + t];
    __syncthreads();

    // q = q_nodes @ Wq + bq  (thread t owns output column t for all 16 nodes)
    float acc[16];
    float b = bq[t];
#pragma unroll
    for (int i = 0; i < 16; i++) acc[i] = b;
    for (int c = 0; c < DIM; c++) {
        float w = Wq[c * DIM + t];
#pragma unroll
        for (int i = 0; i < 16; i++) acc[i] += sqn[i][c] * w;
    }
#pragma unroll
    for (int i = 0; i < 16; i++) sq[i][t] = acc[i];
    __syncthreads();

    const float scale = 0.1767766952966369f;   // 1/sqrt(32)
    // qk[n,h,c] = scale * sum_d q[n,h*32+d] * Wk[c, h*32+d]   (thread t = c)
#pragma unroll
    for (int h = 0; h < HEADS; h++) {
        float a2[16];
#pragma unroll
        for (int i = 0; i < 16; i++) a2[i] = 0.f;
        for (int d = 0; d < DHEAD; d++) {
            float w = g_WkT[(h * DHEAD + d) * DIM + t];
#pragma unroll
            for (int i = 0; i < 16; i++) a2[i] += sq[i][h * DHEAD + d] * w;
        }
#pragma unroll
        for (int i = 0; i < 16; i++)
            g_qk[((size_t)(n0 + i) * HEADS + h) * DIM + t] = a2[i] * scale;
    }
    // qc[n,h] = scale * q[n,h,:].bk[h,:]
    if (t < 64) {
        int i = t >> 2, h = t & 3;
        float a = 0.f;
#pragma unroll
        for (int d = 0; d < DHEAD; d++) a += sq[i][h * DHEAD + d] * bk[h * DHEAD + d];
        g_qc[(size_t)(n0 + i) * HEADS + h] = a * scale;
    }
}

// ---------------- CSR build (edge_index is INT32: JAX default x64-disabled) ----
__global__ void hist_kernel(const int* __restrict__ ei) {
    int e = blockIdx.x * blockDim.x + threadIdx.x;
    if (e < N_EDGES) {
        int d = ei[e];                       // row 0 of (2,E) = dst
        atomicAdd(&g_count[d], 1);
    }
}

__global__ void __launch_bounds__(1024) scan_kernel() {
    __shared__ int part[1024];
    int t = threadIdx.x;
    const int CH = 10;                       // 1024*10 >= 10000
    int base = t * CH;
    int s = 0;
#pragma unroll
    for (int k = 0; k < CH; k++) {
        int i = base + k;
        if (i < N_NODES) s += g_count[i];
    }
    part[t] = s;
    __syncthreads();
    for (int off = 1; off < 1024; off <<= 1) {
        int v = (t >= off) ? part[t - off] : 0;
        __syncthreads();
        part[t] += v;
        __syncthreads();
    }
    int run = part[t] - s;                   // exclusive prefix
#pragma unroll
    for (int k = 0; k < CH; k++) {
        int i = base + k;
        if (i < N_NODES) {
            g_start[i] = run;
            g_cursor[i] = run;
            run += g_count[i];
        }
    }
}

__global__ void scatter_kernel(const int* __restrict__ ei) {
    int e = blockIdx.x * blockDim.x + threadIdx.x;
    if (e < N_EDGES) {
        int d = ei[e];
        int pos = atomicAdd(&g_cursor[d], 1);
        g_elist[pos] = e;
    }
}

// ---------------- fused attention (the hot kernel) ----------------
// One warp per node. Lane l covers v/k feature dims 4l..4l+3 via float4.
// Folded multi-head reduction: 9 SHFL (vs 20) and 1 exp (vs 4) per edge.
// Head accumulators are kept in RELATIVE order: slot j holds head (g ^ j),
// where g = lane>>3 is this lane's "home" head group.
__global__ void __launch_bounds__(256) attn_kernel(const float* __restrict__ k_edges,
                                                   const float* __restrict__ v_edges) {
    int node = blockIdx.x * 8 + (threadIdx.x >> 5);
    if (node >= N_NODES) return;
    int lane = threadIdx.x & 31;
    int g = lane >> 3;                       // home head of this lane's 8-lane group

    const float4* qk4 = reinterpret_cast<const float4*>(g_qk + (size_t)node * HEADS * DIM);
    float rq[HEADS][4];
#pragma unroll
    for (int h = 0; h < HEADS; h++) {
        float4 v = qk4[h * 32 + lane];
        rq[h][0] = v.x; rq[h][1] = v.y; rq[h][2] = v.z; rq[h][3] = v.w;
    }
    float qc_my = g_qc[(size_t)node * HEADS + g];   // only home head's bias needed

    float w[HEADS][4];                        // slot j == head g^j (relative order)
    float denom[HEADS];
#pragma unroll
    for (int j = 0; j < HEADS; j++) {
        denom[j] = 0.f;
        w[j][0] = w[j][1] = w[j][2] = w[j][3] = 0.f;
    }

    int start = g_start[node];
    int cnt = g_count[node];
    const float4* K4 = reinterpret_cast<const float4*>(k_edges);
    const float4* V4 = reinterpret_cast<const float4*>(v_edges);
    const unsigned FULL = 0xffffffffu;
    bool hi16 = (lane & 16) != 0;
    bool hi8  = (lane & 8) != 0;

#pragma unroll 2
    for (int i = 0; i < cnt; i++) {
        int e = g_elist[start + i];
        float4 kf = __ldg(K4 + (size_t)e * 32 + lane);
        float4 vf = __ldg(V4 + (size_t)e * 32 + lane);

        // partial dots (4 dims each) for all 4 heads
        float p0 = kf.x * rq[0][0] + kf.y * rq[0][1] + kf.z * rq[0][2] + kf.w * rq[0][3];
        float p1 = kf.x * rq[1][0] + kf.y * rq[1][1] + kf.z * rq[1][2] + kf.w * rq[1][3];
        float p2 = kf.x * rq[2][0] + kf.y * rq[2][1] + kf.z * rq[2][2] + kf.w * rq[2][3];
        float p3 = kf.x * rq[3][0] + kf.y * rq[3][1] + kf.z * rq[3][2] + kf.w * rq[3][3];

        // fold offset 16: lo half keeps heads {0,1}, hi half keeps heads {2,3}
        float t0 = __shfl_xor_sync(FULL, p0, 16);
        float t1 = __shfl_xor_sync(FULL, p1, 16);
        float t2 = __shfl_xor_sync(FULL, p2, 16);
        float t3 = __shfl_xor_sync(FULL, p3, 16);
        float A = hi16 ? (p2 + t2) : (p0 + t0);
        float B = hi16 ? (p3 + t3) : (p1 + t1);

        // fold offset 8: one head per 8-lane group
        float tA = __shfl_xor_sync(FULL, A, 8);
        float tB = __shfl_xor_sync(FULL, B, 8);
        float S = hi8 ? (B + tB) : (A + tA);

        // reduce within the 8-lane group
        S += __shfl_xor_sync(FULL, S, 4);
        S += __shfl_xor_sync(FULL, S, 2);
        S += __shfl_xor_sync(FULL, S, 1);
        // S = full score of head g (scores ~N(0,1): exp safe in fp32 w/o max-subtract)

        float ex0 = __expf(S + qc_my);                  // head g
        float ex1 = __shfl_xor_sync(FULL, ex0, 8);      // head g^1
        float ex2 = __shfl_xor_sync(FULL, ex0, 16);     // head g^2
        float ex3 = __shfl_xor_sync(FULL, ex1, 16);     // head g^3

        denom[0] += ex0; denom[1] += ex1; denom[2] += ex2; denom[3] += ex3;
        w[0][0] += ex0 * vf.x; w[0][1] += ex0 * vf.y; w[0][2] += ex0 * vf.z; w[0][3] += ex0 * vf.w;
        w[1][0] += ex1 * vf.x; w[1][1] += ex1 * vf.y; w[1][2] += ex1 * vf.z; w[1][3] += ex1 * vf.w;
        w[2][0] += ex2 * vf.x; w[2][1] += ex2 * vf.y; w[2][2] += ex2 * vf.z; w[2][3] += ex2 * vf.w;
        w[3][0] += ex3 * vf.x; w[3][1] += ex3 * vf.y; w[3][2] += ex3 * vf.z; w[3][3] += ex3 * vf.w;
    }

    float4* out4 = reinterpret_cast<float4*>(g_wn + (size_t)node * HEADS * DIM);
#pragma unroll
    for (int j = 0; j < HEADS; j++) {
        int h = g ^ j;                       // un-permute relative slot -> real head
        float inv = (denom[j] > 0.f) ? (1.0f / denom[j]) : 0.f;
        float4 o;
        o.x = w[j][0] * inv; o.y = w[j][1] * inv;
        o.z = w[j][2] * inv; o.w = w[j][3] * inv;
        out4[h * 32 + lane] = o;
    }
}

// ---------------- output GEMM: out[N,128] = wn[N,512] @ M[512,128] + cb ----------------
// 32 nodes x 128 cols per block, 256 threads, 4x4 register tile.
__global__ void __launch_bounds__(256) out_kernel(float* __restrict__ out,
                                                  const float* __restrict__ bo) {
    __shared__ __align__(16) float sAT[32][36];   // [kk][row]
    __shared__ __align__(16) float sM[32][DIM];   // [kk][j]
    int t = threadIdx.x;
    int n0 = blockIdx.x * 32;
    int tr = t >> 5;       // row group 0..7  -> rows tr*4..tr*4+3
    int tc = t & 31;       // col group 0..31 -> cols tc*4..tc*4+3

    float acc[4][4];
#pragma unroll
    for (int r = 0; r < 4; r++)
#pragma unroll
        for (int c = 0; c < 4; c++) acc[r][c] = 0.f;

    for (int k0 = 0; k0 < HEADS * DIM; k0 += 32) {
#pragma unroll
        for (int l = 0; l < 4; l++) {
            int ii = l * 256 + t;
            int row = ii >> 5, kk = ii & 31;
            int n = n0 + row;
            sAT[kk][row] = (n < N_NODES) ? g_wn[(size_t)n * 512 + k0 + kk] : 0.f;
        }
#pragma unroll
        for (int l = 0; l < 16; l++) {
            int ii = l * 256 + t;
            int kk = ii >> 7, jj = ii & 127;
            sM[kk][jj] = g_M[(size_t)(k0 + kk) * DIM + jj];
        }
        __syncthreads();
#pragma unroll
        for (int kk = 0; kk < 32; kk++) {
            float4 a = *reinterpret_cast<const float4*>(&sAT[kk][tr * 4]);
            float4 m = *reinterpret_cast<const float4*>(&sM[kk][tc * 4]);
            acc[0][0] += a.x * m.x; acc[0][1] += a.x * m.y; acc[0][2] += a.x * m.z; acc[0][3] += a.x * m.w;
            acc[1][0] += a.y * m.x; acc[1][1] += a.y * m.y; acc[1][2] += a.y * m.z; acc[1][3] += a.y * m.w;
            acc[2][0] += a.z * m.x; acc[2][1] += a.z * m.y; acc[2][2] += a.z * m.z; acc[2][3] += a.z * m.w;
            acc[3][0] += a.w * m.x; acc[3][1] += a.w * m.y; acc[3][2] += a.w * m.z; acc[3][3] += a.w * m.w;
        }
        __syncthreads();
    }

    float cb4[4], bo4[4];
#pragma unroll
    for (int c = 0; c < 4; c++) {
        cb4[c] = g_cb[tc * 4 + c];
        bo4[c] = bo[tc * 4 + c];
    }
#pragma unroll
    for (int r = 0; r < 4; r++) {
        int n = n0 + tr * 4 + r;
        if (n < N_NODES) {
            bool has = (g_count[n] > 0);
            float4 o;
            o.x = acc[r][0] + (has ? cb4[0] : bo4[0]);
            o.y = acc[r][1] + (has ? cb4[1] : bo4[1]);
            o.z = acc[r][2] + (has ? cb4[2] : bo4[2]);
            o.w = acc[r][3] + (has ? cb4[3] : bo4[3]);
            *reinterpret_cast<float4*>(out + (size_t)n * DIM + tc * 4) = o;
        }
    }
}

// ---------------- launch ----------------
extern "C" void kernel_launch(void* const* d_in, const int* in_sizes, int n_in,
                              void* d_out, int out_size) {
    const float* q_nodes = (const float*)d_in[0];
    const float* k_edges = (const float*)d_in[1];
    const float* v_edges = (const float*)d_in[2];
    const float* Wq = (const float*)d_in[3];
    const float* bq = (const float*)d_in[4];
    const float* Wk = (const float*)d_in[5];
    const float* bk = (const float*)d_in[6];
    const float* Wv = (const float*)d_in[7];
    const float* bv = (const float*)d_in[8];
    const float* Wo = (const float*)d_in[9];
    const float* bo = (const float*)d_in[10];
    const int*   ei = (const int*)d_in[11];     // int32! (JAX x64 disabled)
    float* out = (float*)d_out;

    zero_kernel<<<(N_NODES + 255) / 256, 256>>>();
    wkt_kernel<<<DIM, DIM>>>(Wk);
    m_kernel<<<HEADS * DIM, DIM>>>(Wv, Wo);
    cb_kernel<<<1, DIM>>>(bv, Wo, bo);
    qk_kernel<<<N_NODES / 16, 128>>>(q_nodes, Wq, bq, bk);
    hist_kernel<<<(N_EDGES + 255) / 256, 256>>>(ei);
    scan_kernel<<<1, 1024>>>();
    scatter_kernel<<<(N_EDGES + 255) / 256, 256>>>(ei);
    attn_kernel<<<(N_NODES + 7) / 8, 256>>>(k_edges, v_edges);
    out_kernel<<<(N_NODES + 31) / 32, 256>>>(out, bo);
}

// round 12
// speedup vs baseline: 1.1443x; 1.1443x over previous
#include <cuda_runtime.h>

#define N_NODES 10000
#define N_EDGES 640000
#define DIM 128
#define HEADS 4
#define DHEAD 32

// ---- scratch (device globals; no allocation) ----
__device__ float g_qk[(size_t)N_NODES * HEADS * DIM];   // scale * (Wk^T q) per head, [n][h][c]
__device__ float g_qc[(size_t)N_NODES * HEADS];         // scale * (q . bk) per head
__device__ float g_wn[(size_t)N_NODES * HEADS * DIM];   // normalized weighted v aggregate, [n][h][c]
__device__ int   g_count[N_NODES];
__device__ int   g_start[N_NODES];
__device__ int   g_cursor[N_NODES];
__device__ int   g_elist[N_EDGES];
__device__ float g_WkT[DIM * DIM];                      // WkT[kk][c] = Wk[c][kk]
__device__ float g_M[HEADS * DIM * DIM];                // M[h*128+c][j] = sum_d Wv[c,h32+d]*Wo[h32+d,j]
__device__ float g_cb[DIM];                             // bv@Wo + bo

// ---------------- fused setup kernel ----------------
// blocks [0,512): M precompute; block 512: cb; [513,641): WkT transpose;
// [641,720): zero counts. 128 threads each.
__global__ void __launch_bounds__(128) setup_kernel(const float* __restrict__ Wk,
                                                    const float* __restrict__ Wv,
                                                    const float* __restrict__ Wo,
                                                    const float* __restrict__ bv,
                                                    const float* __restrict__ bo) {
    int b = blockIdx.x;
    int t = threadIdx.x;
    if (b < 512) {
        // M[h*128+c][j] = sum_d Wv[c, h*32+d] * Wo[h*32+d, j]
        int h = b >> 7, c = b & 127;
        float a = 0.f;
#pragma unroll
        for (int d = 0; d < DHEAD; d++)
            a += Wv[c * DIM + h * DHEAD + d] * Wo[(h * DHEAD + d) * DIM + t];
        g_M[b * DIM + t] = a;
    } else if (b == 512) {
        // cb[j] = bo[j] + sum_i bv[i]*Wo[i,j]  (8 independent partials -> MLP 8)
        float a0 = 0.f, a1 = 0.f, a2 = 0.f, a3 = 0.f;
        float a4 = 0.f, a5 = 0.f, a6 = 0.f, a7 = 0.f;
#pragma unroll
        for (int i = 0; i < DIM; i += 8) {
            a0 += bv[i + 0] * Wo[(i + 0) * DIM + t];
            a1 += bv[i + 1] * Wo[(i + 1) * DIM + t];
            a2 += bv[i + 2] * Wo[(i + 2) * DIM + t];
            a3 += bv[i + 3] * Wo[(i + 3) * DIM + t];
            a4 += bv[i + 4] * Wo[(i + 4) * DIM + t];
            a5 += bv[i + 5] * Wo[(i + 5) * DIM + t];
            a6 += bv[i + 6] * Wo[(i + 6) * DIM + t];
            a7 += bv[i + 7] * Wo[(i + 7) * DIM + t];
        }
        g_cb[t] = bo[t] + ((a0 + a1) + (a2 + a3)) + ((a4 + a5) + (a6 + a7));
    } else if (b < 641) {
        int kk = b - 513;
        g_WkT[kk * DIM + t] = Wk[t * DIM + kk];
    } else {
        int i = (b - 641) * 128 + t;
        if (i < N_NODES) g_count[i] = 0;
    }
}

// ---------------- q projection + qk precompute ----------------
// block = 128 threads handles 16 nodes. 10000 % 16 == 0 -> 625 blocks, no guards.
__global__ void __launch_bounds__(128) qk_kernel(const float* __restrict__ q_nodes,
                                                 const float* __restrict__ Wq,
                                                 const float* __restrict__ bq,
                                                 const float* __restrict__ bk) {
    __shared__ float sqn[16][DIM];
    __shared__ float sq[16][DIM];
    int t = threadIdx.x;
    int n0 = blockIdx.x * 16;
#pragma unroll
    for (int i = 0; i < 16; i++) sqn[i][t] = q_nodes[(size_t)(n0 + i) * DIM + t];
    __syncthreads();

    // q = q_nodes @ Wq + bq  (thread t owns output column t for all 16 nodes)
    float acc[16];
    float b = bq[t];
#pragma unroll
    for (int i = 0; i < 16; i++) acc[i] = b;
    for (int c = 0; c < DIM; c++) {
        float w = Wq[c * DIM + t];
#pragma unroll
        for (int i = 0; i < 16; i++) acc[i] += sqn[i][c] * w;
    }
#pragma unroll
    for (int i = 0; i < 16; i++) sq[i][t] = acc[i];
    __syncthreads();

    const float scale = 0.1767766952966369f;   // 1/sqrt(32)
    // qk[n,h,c] = scale * sum_d q[n,h*32+d] * Wk[c, h*32+d]   (thread t = c)
#pragma unroll
    for (int h = 0; h < HEADS; h++) {
        float a2[16];
#pragma unroll
        for (int i = 0; i < 16; i++) a2[i] = 0.f;
        for (int d = 0; d < DHEAD; d++) {
            float w = g_WkT[(h * DHEAD + d) * DIM + t];
#pragma unroll
            for (int i = 0; i < 16; i++) a2[i] += sq[i][h * DHEAD + d] * w;
        }
#pragma unroll
        for (int i = 0; i < 16; i++)
            g_qk[((size_t)(n0 + i) * HEADS + h) * DIM + t] = a2[i] * scale;
    }
    // qc[n,h] = scale * q[n,h,:].bk[h,:]
    if (t < 64) {
        int i = t >> 2, h = t & 3;
        float a = 0.f;
#pragma unroll
        for (int d = 0; d < DHEAD; d++) a += sq[i][h * DHEAD + d] * bk[h * DHEAD + d];
        g_qc[(size_t)(n0 + i) * HEADS + h] = a * scale;
    }
}

// ---------------- CSR build (edge_index is INT32: JAX default x64-disabled) ----
__global__ void hist_kernel(const int* __restrict__ ei) {
    int e = blockIdx.x * blockDim.x + threadIdx.x;
    if (e < N_EDGES) {
        int d = ei[e];                       // row 0 of (2,E) = dst
        atomicAdd(&g_count[d], 1);
    }
}

__global__ void __launch_bounds__(1024) scan_kernel() {
    __shared__ int part[1024];
    int t = threadIdx.x;
    const int CH = 10;                       // 1024*10 >= 10000
    int base = t * CH;
    int s = 0;
#pragma unroll
    for (int k = 0; k < CH; k++) {
        int i = base + k;
        if (i < N_NODES) s += g_count[i];
    }
    part[t] = s;
    __syncthreads();
    for (int off = 1; off < 1024; off <<= 1) {
        int v = (t >= off) ? part[t - off] : 0;
        __syncthreads();
        part[t] += v;
        __syncthreads();
    }
    int run = part[t] - s;                   // exclusive prefix
#pragma unroll
    for (int k = 0; k < CH; k++) {
        int i = base + k;
        if (i < N_NODES) {
            g_start[i] = run;
            g_cursor[i] = run;
            run += g_count[i];
        }
    }
}

__global__ void scatter_kernel(const int* __restrict__ ei) {
    int e = blockIdx.x * blockDim.x + threadIdx.x;
    if (e < N_EDGES) {
        int d = ei[e];
        int pos = atomicAdd(&g_cursor[d], 1);
        g_elist[pos] = e;
    }
}

// ---------------- fused attention (the hot kernel) ----------------
// One warp per node. Lane l covers v/k feature dims 4l..4l+3 via float4.
// Folded multi-head reduction: 9 SHFL + 1 exp per edge; head accumulators in
// RELATIVE order (slot j == head g^j, g = lane>>3).
// Software-pipelined: edge i+1's K/V loads issue before edge i's reduction,
// keeping 4 x 512B loads in flight per warp (covers DRAM latency).
__global__ void __launch_bounds__(256) attn_kernel(const float* __restrict__ k_edges,
                                                   const float* __restrict__ v_edges) {
    int node = blockIdx.x * 8 + (threadIdx.x >> 5);
    if (node >= N_NODES) return;
    int lane = threadIdx.x & 31;
    int g = lane >> 3;                       // home head of this lane's 8-lane group

    const float4* qk4 = reinterpret_cast<const float4*>(g_qk + (size_t)node * HEADS * DIM);
    float rq[HEADS][4];
#pragma unroll
    for (int h = 0; h < HEADS; h++) {
        float4 v = qk4[h * 32 + lane];
        rq[h][0] = v.x; rq[h][1] = v.y; rq[h][2] = v.z; rq[h][3] = v.w;
    }
    float qc_my = g_qc[(size_t)node * HEADS + g];   // only home head's bias needed

    float w[HEADS][4];                        // slot j == head g^j (relative order)
    float denom[HEADS];
#pragma unroll
    for (int j = 0; j < HEADS; j++) {
        denom[j] = 0.f;
        w[j][0] = w[j][1] = w[j][2] = w[j][3] = 0.f;
    }

    int start = g_start[node];
    int cnt = g_count[node];
    const float4* K4 = reinterpret_cast<const float4*>(k_edges);
    const float4* V4 = reinterpret_cast<const float4*>(v_edges);
    const unsigned FULL = 0xffffffffu;
    bool hi16 = (lane & 16) != 0;
    bool hi8  = (lane & 8) != 0;

    if (cnt > 0) {
        int e0 = g_elist[start];
        float4 kf = __ldg(K4 + (size_t)e0 * 32 + lane);
        float4 vf = __ldg(V4 + (size_t)e0 * 32 + lane);

        for (int i = 0; i < cnt; i++) {
            // prefetch next edge (clamped; duplicate last load hits L1)
            int inx = (i + 1 < cnt) ? (i + 1) : i;
            int e1 = g_elist[start + inx];
            float4 kn = __ldg(K4 + (size_t)e1 * 32 + lane);
            float4 vn = __ldg(V4 + (size_t)e1 * 32 + lane);

            // partial dots (4 dims each) for all 4 heads
            float p0 = kf.x * rq[0][0] + kf.y * rq[0][1] + kf.z * rq[0][2] + kf.w * rq[0][3];
            float p1 = kf.x * rq[1][0] + kf.y * rq[1][1] + kf.z * rq[1][2] + kf.w * rq[1][3];
            float p2 = kf.x * rq[2][0] + kf.y * rq[2][1] + kf.z * rq[2][2] + kf.w * rq[2][3];
            float p3 = kf.x * rq[3][0] + kf.y * rq[3][1] + kf.z * rq[3][2] + kf.w * rq[3][3];

            // fold offset 16: lo half keeps heads {0,1}, hi half keeps heads {2,3}
            float t0 = __shfl_xor_sync(FULL, p0, 16);
            float t1 = __shfl_xor_sync(FULL, p1, 16);
            float t2 = __shfl_xor_sync(FULL, p2, 16);
            float t3 = __shfl_xor_sync(FULL, p3, 16);
            float A = hi16 ? (p2 + t2) : (p0 + t0);
            float B = hi16 ? (p3 + t3) : (p1 + t1);

            // fold offset 8: one head per 8-lane group
            float tA = __shfl_xor_sync(FULL, A, 8);
            float tB = __shfl_xor_sync(FULL, B, 8);
            float S = hi8 ? (B + tB) : (A + tA);

            // reduce within the 8-lane group
            S += __shfl_xor_sync(FULL, S, 4);
            S += __shfl_xor_sync(FULL, S, 2);
            S += __shfl_xor_sync(FULL, S, 1);
            // S = full score of head g (scores ~N(0,1): exp safe w/o max-subtract)

            float ex0 = __expf(S + qc_my);                  // head g
            float ex1 = __shfl_xor_sync(FULL, ex0, 8);      // head g^1
            float ex2 = __shfl_xor_sync(FULL, ex0, 16);     // head g^2
            float ex3 = __shfl_xor_sync(FULL, ex1, 16);     // head g^3

            denom[0] += ex0; denom[1] += ex1; denom[2] += ex2; denom[3] += ex3;
            w[0][0] += ex0 * vf.x; w[0][1] += ex0 * vf.y; w[0][2] += ex0 * vf.z; w[0][3] += ex0 * vf.w;
            w[1][0] += ex1 * vf.x; w[1][1] += ex1 * vf.y; w[1][2] += ex1 * vf.z; w[1][3] += ex1 * vf.w;
            w[2][0] += ex2 * vf.x; w[2][1] += ex2 * vf.y; w[2][2] += ex2 * vf.z; w[2][3] += ex2 * vf.w;
            w[3][0] += ex3 * vf.x; w[3][1] += ex3 * vf.y; w[3][2] += ex3 * vf.z; w[3][3] += ex3 * vf.w;

            kf = kn; vf = vn;
        }
    }

    float4* out4 = reinterpret_cast<float4*>(g_wn + (size_t)node * HEADS * DIM);
#pragma unroll
    for (int j = 0; j < HEADS; j++) {
        int h = g ^ j;                       // un-permute relative slot -> real head
        float inv = (denom[j] > 0.f) ? (1.0f / denom[j]) : 0.f;
        float4 o;
        o.x = w[j][0] * inv; o.y = w[j][1] * inv;
        o.z = w[j][2] * inv; o.w = w[j][3] * inv;
        out4[h * 32 + lane] = o;
    }
}

// ---------------- output GEMM: out[N,128] = wn[N,512] @ M[512,128] + cb ----------------
// 32 nodes x 128 cols per block, 256 threads, 4x4 register tile.
__global__ void __launch_bounds__(256) out_kernel(float* __restrict__ out,
                                                  const float* __restrict__ bo) {
    __shared__ __align__(16) float sAT[32][36];   // [kk][row]
    __shared__ __align__(16) float sM[32][DIM];   // [kk][j]
    int t = threadIdx.x;
    int n0 = blockIdx.x * 32;
    int tr = t >> 5;       // row group 0..7  -> rows tr*4..tr*4+3
    int tc = t & 31;       // col group 0..31 -> cols tc*4..tc*4+3

    float acc[4][4];
#pragma unroll
    for (int r = 0; r < 4; r++)
#pragma unroll
        for (int c = 0; c < 4; c++) acc[r][c] = 0.f;

    for (int k0 = 0; k0 < HEADS * DIM; k0 += 32) {
#pragma unroll
        for (int l = 0; l < 4; l++) {
            int ii = l * 256 + t;
            int row = ii >> 5, kk = ii & 31;
            int n = n0 + row;
            sAT[kk][row] = (n < N_NODES) ? g_wn[(size_t)n * 512 + k0 + kk] : 0.f;
        }
#pragma unroll
        for (int l = 0; l < 16; l++) {
            int ii = l * 256 + t;
            int kk = ii >> 7, jj = ii & 127;
            sM[kk][jj] = g_M[(size_t)(k0 + kk) * DIM + jj];
        }
        __syncthreads();
#pragma unroll
        for (int kk = 0; kk < 32; kk++) {
            float4 a = *reinterpret_cast<const float4*>(&sAT[kk][tr * 4]);
            float4 m = *reinterpret_cast<const float4*>(&sM[kk][tc * 4]);
            acc[0][0] += a.x * m.x; acc[0][1] += a.x * m.y; acc[0][2] += a.x * m.z; acc[0][3] += a.x * m.w;
            acc[1][0] += a.y * m.x; acc[1][1] += a.y * m.y; acc[1][2] += a.y * m.z; acc[1][3] += a.y * m.w;
            acc[2][0] += a.z * m.x; acc[2][1] += a.z * m.y; acc[2][2] += a.z * m.z; acc[2][3] += a.z * m.w;
            acc[3][0] += a.w * m.x; acc[3][1] += a.w * m.y; acc[3][2] += a.w * m.z; acc[3][3] += a.w * m.w;
        }
        __syncthreads();
    }

    float cb4[4], bo4[4];
#pragma unroll
    for (int c = 0; c < 4; c++) {
        cb4[c] = g_cb[tc * 4 + c];
        bo4[c] = bo[tc * 4 + c];
    }
#pragma unroll
    for (int r = 0; r < 4; r++) {
        int n = n0 + tr * 4 + r;
        if (n < N_NODES) {
            bool has = (g_count[n] > 0);
            float4 o;
            o.x = acc[r][0] + (has ? cb4[0] : bo4[0]);
            o.y = acc[r][1] + (has ? cb4[1] : bo4[1]);
            o.z = acc[r][2] + (has ? cb4[2] : bo4[2]);
            o.w = acc[r][3] + (has ? cb4[3] : bo4[3]);
            *reinterpret_cast<float4*>(out + (size_t)n * DIM + tc * 4) = o;
        }
    }
}

// ---------------- launch ----------------
extern "C" void kernel_launch(void* const* d_in, const int* in_sizes, int n_in,
                              void* d_out, int out_size) {
    const float* q_nodes = (const float*)d_in[0];
    const float* k_edges = (const float*)d_in[1];
    const float* v_edges = (const float*)d_in[2];
    const float* Wq = (const float*)d_in[3];
    const float* bq = (const float*)d_in[4];
    const float* Wk = (const float*)d_in[5];
    const float* bk = (const float*)d_in[6];
    const float* Wv = (const float*)d_in[7];
    const float* bv = (const float*)d_in[8];
    const float* Wo = (const float*)d_in[9];
    const float* bo = (const float*)d_in[10];
    const int*   ei = (const int*)d_in[11];     // int32! (JAX x64 disabled)
    float* out = (float*)d_out;

    setup_kernel<<<720, 128>>>(Wk, Wv, Wo, bv, bo);               // 1
    qk_kernel<<<N_NODES / 16, 128>>>(q_nodes, Wq, bq, bk);        // 2
    hist_kernel<<<(N_EDGES + 255) / 256, 256>>>(ei);              // 3
    scan_kernel<<<1, 1024>>>();                                   // 4
    scatter_kernel<<<(N_EDGES + 255) / 256, 256>>>(ei);           // 5
    attn_kernel<<<(N_NODES + 7) / 8, 256>>>(k_edges, v_edges);    // 6 <- ncu -s 5 target
    out_kernel<<<(N_NODES + 31) / 32, 256>>>(out, bo);            // 7
}